// round 1
// baseline (speedup 1.0000x reference)
#include <cuda_runtime.h>
#include <math.h>

#define NPTS 16384
#define DIM  64
#define NC   9
#define TILE 64

// ---- device scratch (no allocations allowed) ----
__device__ float g_fn[NPTS * DIM];     // normalized features
__device__ int   g_cls[NPTS];          // class 1..8 if valid member, else 0
__device__ int   g_cidx[NPTS];         // compacted point indices
__device__ int   g_ccls[NPTS];         // compacted classes
__device__ int   g_nvalid;
__device__ int   g_cnt[NC];
__device__ float g_sum[NC * DIM];      // per-class feature sums
__device__ float g_cross[NC * NC];     // relu(dot) sums per unordered class pair

// ---------------- K0: zero accumulators ----------------
__global__ void k0_zero() {
    int t = threadIdx.x;
    if (t < NC) g_cnt[t] = 0;
    if (t < NC * NC) g_cross[t] = 0.f;
    for (int i = t; i < NC * DIM; i += blockDim.x) g_sum[i] = 0.f;
    if (t == 0) g_nvalid = 0;
}

// ---------------- K1: classify + normalize (1 warp / point) ----------------
__global__ void k1_classify(const int* __restrict__ labels,
                            const float* __restrict__ feats,
                            const float* __restrict__ scores) {
    int warp = (blockIdx.x * blockDim.x + threadIdx.x) >> 5;
    int lane = threadIdx.x & 31;
    if (warp >= NPTS) return;
    int p = warp;

    // feature row: 64 floats, 2 per lane, coalesced
    float x0 = feats[p * DIM + lane];
    float x1 = feats[p * DIM + 32 + lane];
    float ss = x0 * x0 + x1 * x1;
    #pragma unroll
    for (int o = 16; o > 0; o >>= 1) ss += __shfl_xor_sync(0xffffffffu, ss, o);
    float inv = 1.0f / fmaxf(sqrtf(ss), 1e-12f);

    // softmax argmax + max prob (9 classes on first 9 lanes)
    float s = (lane < NC) ? scores[p * NC + lane] : -INFINITY;
    float mval = s; int midx = lane;
    #pragma unroll
    for (int o = 16; o > 0; o >>= 1) {
        float ov = __shfl_xor_sync(0xffffffffu, mval, o);
        int   oi = __shfl_xor_sync(0xffffffffu, midx, o);
        if (ov > mval || (ov == mval && oi < midx)) { mval = ov; midx = oi; }
    }
    float e = (lane < NC) ? expf(s - mval) : 0.f;
    #pragma unroll
    for (int o = 16; o > 0; o >>= 1) e += __shfl_xor_sync(0xffffffffu, e, o);
    float pmax = 1.0f / e;   // exp(smax - smax) / sum(exp)

    int lab = labels[p];
    int valid = (lab == midx) && (pmax >= 0.5f);
    int cls = (valid && lab >= 1) ? lab : 0;

    float f0 = x0 * inv, f1 = x1 * inv;
    g_fn[p * DIM + lane]      = f0;
    g_fn[p * DIM + 32 + lane] = f1;
    if (lane == 0) g_cls[p] = cls;

    if (cls > 0) {
        atomicAdd(&g_sum[cls * DIM + lane],      f0);
        atomicAdd(&g_sum[cls * DIM + 32 + lane], f1);
        if (lane == 0) atomicAdd(&g_cnt[cls], 1);
    }
}

// ---------------- K2: deterministic compaction (single block) ----------------
__global__ void k2_compact() {
    __shared__ int wsum[32];
    __shared__ int woff[32];
    __shared__ int s_total;
    int tid = threadIdx.x, lane = tid & 31, wid = tid >> 5;
    int base = 0;
    for (int start = 0; start < NPTS; start += 1024) {
        int p = start + tid;
        int c = g_cls[p];
        int f = (c > 0);
        unsigned bal = __ballot_sync(0xffffffffu, f);
        int pre = __popc(bal & ((1u << lane) - 1u));
        if (lane == 0) wsum[wid] = __popc(bal);
        __syncthreads();
        if (wid == 0) {
            int v = wsum[lane];
            int inc = v;
            #pragma unroll
            for (int o = 1; o < 32; o <<= 1) {
                int t2 = __shfl_up_sync(0xffffffffu, inc, o);
                if (lane >= o) inc += t2;
            }
            woff[lane] = inc - v;
            if (lane == 31) s_total = inc;
        }
        __syncthreads();
        if (f) {
            int pos = base + woff[wid] + pre;
            g_cidx[pos] = p;
            g_ccls[pos] = c;
        }
        base += s_total;
        __syncthreads();
    }
    if (tid == 0) g_nvalid = base;
}

// ---------------- K3: pairwise relu(dot) over compacted points ----------------
__global__ void k3_pairs() {
    __shared__ float As[TILE][DIM + 4];
    __shared__ float Bs[TILE][DIM + 4];
    __shared__ int   acl[TILE], bcl[TILE];
    __shared__ float scross[NC * NC];

    int tid = threadIdx.x;
    for (int i = tid; i < NC * NC; i += blockDim.x) scross[i] = 0.f;

    int nv = g_nvalid;
    int nt = (nv + TILE - 1) / TILE;
    long long ntp = (long long)nt * (nt + 1) / 2;

    for (long long k = blockIdx.x; k < ntp; k += gridDim.x) {
        // decode k -> (ti <= tj), k = tj*(tj+1)/2 + ti
        int tj = (int)((sqrtf(8.0f * (float)k + 1.0f) - 1.0f) * 0.5f);
        while ((long long)(tj + 1) * (tj + 2) / 2 <= k) tj++;
        while ((long long)tj * (tj + 1) / 2 > k) tj--;
        int ti = (int)(k - (long long)tj * (tj + 1) / 2);

        __syncthreads();  // protect smem from previous iteration

        // load tiles (gathered): 64 rows x 16 float4 each = 1024 float4 per tile
        for (int q = tid; q < TILE * (DIM / 4); q += blockDim.x) {
            int row = q >> 4, c4 = q & 15;
            {
                int v = ti * TILE + row;
                float4 val = make_float4(0.f, 0.f, 0.f, 0.f);
                if (v < nv) val = *(const float4*)&g_fn[g_cidx[v] * DIM + c4 * 4];
                *(float4*)&As[row][c4 * 4] = val;
            }
            {
                int v = tj * TILE + row;
                float4 val = make_float4(0.f, 0.f, 0.f, 0.f);
                if (v < nv) val = *(const float4*)&g_fn[g_cidx[v] * DIM + c4 * 4];
                *(float4*)&Bs[row][c4 * 4] = val;
            }
        }
        if (tid < TILE) {
            int va = ti * TILE + tid;
            int vb = tj * TILE + tid;
            acl[tid] = (va < nv) ? g_ccls[va] : 0;
            bcl[tid] = (vb < nv) ? g_ccls[vb] : 0;
        }
        __syncthreads();

        // 4096 pairs / 256 threads = 16 pairs each
        for (int p = tid; p < TILE * TILE; p += blockDim.x) {
            int i = p >> 6, j = p & 63;
            if (ti == tj && i >= j) continue;        // i<j on diagonal tiles
            int ci = acl[i], cj = bcl[j];
            if (ci == cj) continue;                  // same-class & padding: not used
            float acc = 0.f;
            #pragma unroll
            for (int d4 = 0; d4 < DIM / 4; d4++) {
                float4 a = *(float4*)&As[i][d4 * 4];
                float4 b = *(float4*)&Bs[j][d4 * 4];
                acc += a.x * b.x + a.y * b.y + a.z * b.z + a.w * b.w;
            }
            if (acc > 0.f) {
                int lo = min(ci, cj), hi = max(ci, cj);
                atomicAdd(&scross[lo * NC + hi], acc);
            }
        }
    }
    __syncthreads();
    for (int i = tid; i < NC * NC; i += blockDim.x)
        if (scross[i] != 0.f) atomicAdd(&g_cross[i], scross[i]);
}

// ---------------- K4: finalize ----------------
__global__ void k4_final(float* __restrict__ out) {
    __shared__ float red[64];
    int tid = threadIdx.x;
    float acc = 0.f;

    // pull: classes 1..8
    if (tid >= 1 && tid < NC) {
        float cnt = (float)g_cnt[tid];
        float quad = 0.f;
        #pragma unroll
        for (int d = 0; d < DIM; d++) {
            float v = g_sum[tid * DIM + d];
            quad += v * v;
        }
        float npairs = cnt * (cnt - 1.0f) * 0.5f;
        if (npairs > 0.f)
            acc += 1.0f - ((quad - cnt) * 0.5f) / npairs;
    }
    // push: unordered class pairs a<b
    for (int idx = tid; idx < NC * NC; idx += 64) {
        int a = idx / NC, b = idx % NC;
        if (a >= 1 && b > a) {
            float den = (float)g_cnt[a] * (float)g_cnt[b];
            if (den > 0.f) acc += g_cross[a * NC + b] / den;
        }
    }
    red[tid] = acc;
    __syncthreads();
    #pragma unroll
    for (int o = 32; o > 0; o >>= 1) {
        if (tid < o) red[tid] += red[tid + o];
        __syncthreads();
    }
    if (tid == 0) out[0] = red[0];
}

extern "C" void kernel_launch(void* const* d_in, const int* in_sizes, int n_in,
                              void* d_out, int out_size) {
    const int*   labels = nullptr;
    const float* feats  = nullptr;
    const float* scores = nullptr;
    for (int i = 0; i < n_in; i++) {
        if (in_sizes[i] == NPTS)            labels = (const int*)d_in[i];
        else if (in_sizes[i] == NPTS * DIM) feats  = (const float*)d_in[i];
        else if (in_sizes[i] == NPTS * NC)  scores = (const float*)d_in[i];
    }
    float* out = (float*)d_out;

    k0_zero<<<1, 256>>>();
    k1_classify<<<(NPTS * 32) / 256, 256>>>(labels, feats, scores);
    k2_compact<<<1, 1024>>>();
    k3_pairs<<<148, 256>>>();
    k4_final<<<1, 64>>>(out);
}